// round 6
// baseline (speedup 1.0000x reference)
#include <cuda_runtime.h>
#include <cub/cub.cuh>
#include <cstdint>

#define BATCH  16
#define NP     25200
#define TOPKN  2048
#define MAXDET 1000
#define CANDN  3072
#define ECAP   6144
#define SC_THREADS 1024
#define SC_ITEMS   3
#define FULLM  0xffffffffu
typedef unsigned long long u64;

// ---------------- scratch (static device globals) ----------------
__device__ u64      g_keys[BATCH * NP];        // idx(15) | inv(25)<<15 | cls(7)<<40
__device__ int      g_hist[BATCH * 132];       // bucket = inv>>17 (valid only); reset in k_sortcompact
__device__ float4   g_boxes[BATCH * TOPKN];    // unshifted xyxy, rank-ordered
__device__ float    g_scores[BATCH * TOPKN];
__device__ float    g_clsf[BATCH * TOPKN];
__device__ unsigned g_clsmem[BATCH * TOPKN];   // class-grouped: rank | (cls<<16)
__device__ int      g_clsbase[BATCH * 81];     // per-class segment offsets (+ total at [80])

// ---------------- stage 1: score/class, pack key, bucket histogram ----------------
__global__ void k_score(const float* __restrict__ pred, u64* __restrict__ keys) {
    int gw   = (blockIdx.x * blockDim.x + threadIdx.x) >> 5;
    int lane = threadIdx.x & 31;
    if (gw >= BATCH * NP) return;
    const float* p = pred + (size_t)gw * 85;

    float v0 = p[lane];
    float v1 = p[lane + 32];
    float v2 = (lane < 21) ? p[lane + 64] : -1.0f;
    float obj = __shfl_sync(FULLM, v0, 4);

    float bv = (lane >= 5) ? v0 : -1.0f;
    int   bi = lane;
    if (v1 > bv) { bv = v1; bi = lane + 32; }
    if (v2 > bv) { bv = v2; bi = lane + 64; }
    #pragma unroll
    for (int off = 16; off; off >>= 1) {
        float ov = __shfl_down_sync(FULLM, bv, off);
        int   oi = __shfl_down_sync(FULLM, bi, off);
        if (ov > bv || (ov == bv && oi < bi)) { bv = ov; bi = oi; }
    }
    if (lane == 0) {
        float score = __fmul_rn(obj, bv);
        bool  valid = (obj > 0.25f) && (score > 0.25f);
        int b = gw / NP;
        int i = gw - b * NP;
        int cls = bi - 5;
        unsigned inv;
        if (valid) {
            inv = 0x3F800000u - __float_as_uint(score);   // < 0x1000000 when score > 0.25
            atomicAdd(&g_hist[b * 132 + (inv >> 17)], 1);
        } else {
            inv = 0x1000000u;                             // invalid marker
        }
        keys[gw] = (u64)i | ((u64)inv << 15) | ((u64)cls << 40);
    }
}

// ---------------- stage 2: cutoff + chunked ordered compact + sort + gather + class-group ----------------
__global__ void __launch_bounds__(SC_THREADS)
k_sortcompact(const float* __restrict__ pred) {
    typedef cub::BlockRadixSort<unsigned, SC_THREADS, SC_ITEMS, unsigned> BRS;
    __shared__ union {
        struct { unsigned ck[CANDN]; unsigned cv[CANDN]; } c;
        typename BRS::TempStorage sort;
    } u;
    __shared__ int s_hist[128];
    __shared__ int s_cut_sh, s_M;
    __shared__ int s_wsum[32];
    __shared__ int s_ccnt[81], s_cofs[81];

    int b = blockIdx.x, t = threadIdx.x;
    int lane = t & 31, wid = t >> 5;

    if (t < 128) { s_hist[t] = g_hist[b * 132 + t]; g_hist[b * 132 + t] = 0; }
    __syncthreads();
    if (t == 0) {
        int cum = 0, c = 128;
        for (int i = 0; i < 128; i++) {
            cum += s_hist[i];
            if (cum >= TOPKN) { c = i; break; }
        }
        s_cut_sh = c;
    }
    __syncthreads();
    int cut = s_cut_sh;

    // chunked idx-ordered compaction: thread t owns items [25t, 25t+25)
    const int CHUNK = (NP + SC_THREADS - 1) / SC_THREADS;   // 25
    int start = t * CHUNK;
    int lim = min(start + CHUNK, NP);
    int cnt = 0;
    for (int i = start; i < lim; i++) {
        unsigned inv = (unsigned)((g_keys[(size_t)b * NP + i] >> 15) & 0x1FFFFFFull);
        if (inv < 0x1000000u && (int)(inv >> 17) <= cut) cnt++;
    }
    int incl = cnt;
    #pragma unroll
    for (int d = 1; d < 32; d <<= 1) {
        int n = __shfl_up_sync(FULLM, incl, d);
        if (lane >= d) incl += n;
    }
    if (lane == 31) s_wsum[wid] = incl;
    __syncthreads();
    if (t < 32) {
        int v = s_wsum[t], inc2 = v;
        #pragma unroll
        for (int d = 1; d < 32; d <<= 1) {
            int n = __shfl_up_sync(FULLM, inc2, d);
            if (t >= d) inc2 += n;
        }
        s_wsum[t] = inc2 - v;
        if (t == 31) s_M = inc2;
    }
    __syncthreads();
    int off = s_wsum[wid] + incl - cnt;
    for (int i = start; i < lim; i++) {
        u64 key = g_keys[(size_t)b * NP + i];
        unsigned inv = (unsigned)((key >> 15) & 0x1FFFFFFull);
        if (inv < 0x1000000u && (int)(inv >> 17) <= cut) {
            if (off < CANDN) {
                u.c.ck[off] = inv;
                u.c.cv[off] = (unsigned)(key & 0x7FFFull) |
                              ((unsigned)((key >> 40) & 0x7Full) << 16);
            }
            off++;
        }
    }
    __syncthreads();
    int M = min(s_M, CANDN);

    unsigned keys[SC_ITEMS], vals[SC_ITEMS];
    #pragma unroll
    for (int i = 0; i < SC_ITEMS; i++) {
        int r = t * SC_ITEMS + i;
        keys[i] = (r < M) ? u.c.ck[r] : 0x1FFFFFFu;   // padding sorts last
        vals[i] = (r < M) ? u.c.cv[r] : 0u;
    }
    __syncthreads();
    // stable ascending sort on 25-bit inv; idx-order compaction supplies the tie-break
    BRS(u.sort).Sort(keys, vals, 0, 25);

    if (t < 81) s_ccnt[t] = 0;
    __syncthreads();

    #pragma unroll
    for (int i = 0; i < SC_ITEMS; i++) {
        int r = t * SC_ITEMS + i;
        if (r >= TOPKN) continue;
        int g = b * TOPKN + r;
        unsigned inv = keys[i];
        if (inv >= 0x1000000u) {          // padding: no real candidate at this rank
            g_boxes[g]  = make_float4(0.f, 0.f, 0.f, 0.f);
            g_scores[g] = 0.f;
            g_clsf[g]   = 0.f;
            continue;
        }
        int idx = (int)(vals[i] & 0xFFFFu);
        int cls = (int)(vals[i] >> 16);
        float s = __uint_as_float(0x3F800000u - inv);

        const float* p = pred + ((size_t)b * NP + idx) * 85;
        float cx = p[0], cy = p[1], w = p[2], h = p[3];
        float x1 = __fsub_rn(cx, __fmul_rn(w, 0.5f));
        float y1 = __fsub_rn(cy, __fmul_rn(h, 0.5f));
        float x2 = __fadd_rn(cx, __fmul_rn(w, 0.5f));
        float y2 = __fadd_rn(cy, __fmul_rn(h, 0.5f));

        g_boxes[g]  = make_float4(x1, y1, x2, y2);
        g_scores[g] = s;
        g_clsf[g]   = (float)cls;
        atomicAdd(&s_ccnt[cls], 1);
    }
    __syncthreads();
    if (t == 0) {
        int run = 0;
        for (int c = 0; c < 80; c++) { s_cofs[c] = run; run += s_ccnt[c]; }
        s_cofs[80] = run;
    }
    __syncthreads();
    if (t < 81) g_clsbase[b * 81 + t] = s_cofs[t];
    if (t < 80) s_ccnt[t] = s_cofs[t];   // reuse as running positions
    __syncthreads();
    #pragma unroll
    for (int i = 0; i < SC_ITEMS; i++) {
        int r = t * SC_ITEMS + i;
        if (r >= TOPKN || keys[i] >= 0x1000000u) continue;
        int cls = (int)(vals[i] >> 16);
        int slot = atomicAdd(&s_ccnt[cls], 1);
        g_clsmem[b * TOPKN + slot] = (unsigned)r | ((unsigned)cls << 16);
    }
}

// ---------------- stage 3: within-class IoU edges + Jacobi greedy + output (fused) ----------------
__global__ void __launch_bounds__(256) k_nms(float* __restrict__ out) {
    extern __shared__ char dyn[];
    float4*         s_box   = (float4*)dyn;                          // 2048*16 = 32768
    unsigned*       s_edges = (unsigned*)(dyn + 32768);              // 6144*4  = 24576
    unsigned short* s_rank  = (unsigned short*)(dyn + 32768 + 24576);// 2048*2  = 4096
    int*            s_cb    = (int*)(dyn + 32768 + 24576 + 4096);    // 81*4
    __shared__ int s_ecnt, s_changed;
    __shared__ u64 s_keep[32], s_sup[32];
    __shared__ unsigned s_wbase[32];
    __shared__ unsigned s_total;

    int b = blockIdx.x, t = threadIdx.x;
    int lane = t & 31, wid = t >> 5;

    if (t < 81) s_cb[t] = g_clsbase[b * 81 + t];
    if (t == 0) s_ecnt = 0;
    __syncthreads();
    int total = s_cb[80];

    // load class-grouped, class-shifted boxes
    for (int m = t; m < total; m += 256) {
        unsigned e = g_clsmem[b * TOPKN + m];
        int r = (int)(e & 0xFFFFu), cls = (int)(e >> 16);
        float4 bx = g_boxes[b * TOPKN + r];
        float c = __fmul_rn((float)cls, 4096.0f);
        s_box[m] = make_float4(__fadd_rn(bx.x, c), __fadd_rn(bx.y, c),
                               __fadd_rn(bx.z, c), __fadd_rn(bx.w, c));
        s_rank[m] = (unsigned short)r;
    }
    __syncthreads();

    // within-class pair IoU; one warp per class (round-robin)
    for (int c = wid; c < 80; c += 8) {
        int lo = s_cb[c], n = s_cb[c + 1] - lo;
        for (int j = 1 + lane; j < n; j += 32) {
            float4 A = s_box[lo + j];
            float areaA = __fmul_rn(__fsub_rn(A.z, A.x), __fsub_rn(A.w, A.y));
            int rj = s_rank[lo + j];
            for (int i = 0; i < j; i++) {
                float4 B = s_box[lo + i];
                float ltx = fmaxf(A.x, B.x);
                float lty = fmaxf(A.y, B.y);
                float rbx = fminf(A.z, B.z);
                float rby = fminf(A.w, B.w);
                float ww = fmaxf(__fsub_rn(rbx, ltx), 0.0f);
                float hh = fmaxf(__fsub_rn(rby, lty), 0.0f);
                float inter = __fmul_rn(ww, hh);
                if (inter > 0.0f) {
                    float areaB = __fmul_rn(__fsub_rn(B.z, B.x), __fsub_rn(B.w, B.y));
                    float denom = __fadd_rn(__fsub_rn(__fadd_rn(areaA, areaB), inter), 1e-7f);
                    bool bit;
                    if (inter > __fmul_rn(0.4501f, denom))       bit = true;
                    else if (inter <= __fmul_rn(0.4499f, denom)) bit = false;
                    else bit = (__fdiv_rn(inter, denom) > 0.45f);
                    if (bit) {
                        int ri = s_rank[lo + i];
                        int lw = min(ri, rj), hi = max(ri, rj);
                        int pos = atomicAdd(&s_ecnt, 1);
                        if (pos < ECAP)
                            s_edges[pos] = ((unsigned)lw << 16) | (unsigned)hi;
                    }
                }
            }
        }
    }
    __syncthreads();
    int E = min(s_ecnt, ECAP);

    // valid = rank < total (ranks are score-sorted; all real candidates are valid)
    if (t < 32) {
        int base = t * 64;
        s_keep[t] = (total >= base + 64) ? ~0ull
                  : (total <= base) ? 0ull : ((1ull << (total - base)) - 1ull);
    }
    __syncthreads();

    // Jacobi fixpoint of keep[j] = valid[j] & !exists edge(i,j) with keep[i] (DAG, i<j)
    int changed;
    do {
        if (t < 32) s_sup[t] = 0ull;
        __syncthreads();
        for (int e = t; e < E; e += 256) {
            unsigned ed = s_edges[e];
            int i = (int)(ed >> 16), j = (int)(ed & 0xFFFFu);
            if ((s_keep[i >> 6] >> (i & 63)) & 1ull)
                atomicOr(&s_sup[j >> 6], 1ull << (j & 63));
        }
        __syncthreads();
        if (t == 0) s_changed = 0;
        __syncthreads();
        if (t < 32) {
            int base = t * 64;
            u64 valid = (total >= base + 64) ? ~0ull
                      : (total <= base) ? 0ull : ((1ull << (total - base)) - 1ull);
            u64 nk = valid & ~s_sup[t];
            if (nk != s_keep[t]) { s_keep[t] = nk; s_changed = 1; }
        }
        __syncthreads();
        changed = s_changed;
    } while (changed);

    // per-word base ranks
    if (wid == 0) {
        unsigned cnt = (unsigned)__popcll(s_keep[lane]), incl = cnt;
        #pragma unroll
        for (int d = 1; d < 32; d <<= 1) {
            unsigned n = __shfl_up_sync(FULLM, incl, d);
            if (lane >= d) incl += n;
        }
        s_wbase[lane] = incl - cnt;
        if (lane == 31) s_total = incl;
    }
    __syncthreads();

    // parallel compaction of survivors (rank order == score order)
    #pragma unroll
    for (int r = 0; r < 8; r++) {
        int gbit = t + 256 * r;
        int word = gbit >> 6, bit = gbit & 63;
        u64 kw = s_keep[word];
        if ((kw >> bit) & 1ull) {
            unsigned rank = s_wbase[word] +
                            (unsigned)__popcll(kw & (((u64)1 << bit) - 1ull));
            if (rank < MAXDET) {
                int g = b * TOPKN + gbit;
                float4 bx = g_boxes[g];
                float* o = out + ((size_t)b * MAXDET + rank) * 6;
                o[0] = bx.x; o[1] = bx.y; o[2] = bx.z; o[3] = bx.w;
                o[4] = g_scores[g];
                o[5] = g_clsf[g];
            }
        }
    }
    unsigned fillstart = min(s_total, (unsigned)MAXDET);
    for (unsigned m = fillstart + t; m < MAXDET; m += 256) {
        float* o = out + ((size_t)b * MAXDET + m) * 6;
        o[0] = 0.f; o[1] = 0.f; o[2] = 0.f; o[3] = 0.f; o[4] = 0.f; o[5] = -1.f;
    }
}

// ---------------- launch ----------------
extern "C" void kernel_launch(void* const* d_in, const int* in_sizes, int n_in,
                              void* d_out, int out_size) {
    (void)in_sizes; (void)n_in; (void)out_size;
    const float* pred = (const float*)d_in[0];
    float* out = (float*)d_out;

    const int DYN = 32768 + 24576 + 4096 + 81 * 4;
    static bool attr_set = false;
    if (!attr_set) {
        cudaFuncSetAttribute(k_nms, cudaFuncAttributeMaxDynamicSharedMemorySize, DYN);
        attr_set = true;
    }

    void* keys_p;
    cudaGetSymbolAddress(&keys_p, g_keys);

    {   // stage 1
        int warps = BATCH * NP;
        int threads = 256;
        int blocks = (warps * 32 + threads - 1) / threads;
        k_score<<<blocks, threads>>>(pred, (u64*)keys_p);
    }
    k_sortcompact<<<BATCH, SC_THREADS>>>(pred);
    k_nms<<<BATCH, 256, DYN>>>(out);
}

// round 7
// speedup vs baseline: 1.2889x; 1.2889x over previous
#include <cuda_runtime.h>
#include <cub/cub.cuh>
#include <cstdint>

#define BATCH  16
#define NP     25200
#define TOPKN  2048
#define MAXDET 1000
#define CANDN  3072
#define ECAP   6144
#define IPB    128
#define SC_THREADS 1024
#define SC_ITEMS   3
#define FULLM  0xffffffffu
typedef unsigned long long u64;

// ---------------- scratch (static device globals) ----------------
__device__ unsigned g_key32[BATCH * NP];       // (inv<<7)|cls, 0xFFFFFFFF = invalid
__device__ int      g_hist[BATCH * 132];       // bucket = inv>>17 (valid only); reset in k_sortcompact
__device__ float4   g_boxes[BATCH * TOPKN];    // unshifted xyxy, rank-ordered
__device__ float    g_scores[BATCH * TOPKN];
__device__ float    g_clsf[BATCH * TOPKN];
__device__ unsigned g_clsmem[BATCH * TOPKN];   // class-grouped: rank | (cls<<16)
__device__ int      g_clsbase[BATCH * 81];     // per-class segment offsets (+ total at [80])

// ---------------- stage 1: tiled score/class/key ----------------
__global__ void __launch_bounds__(256) k_score(const float* __restrict__ pred) {
    __shared__ float s_data[IPB * 85 + 4];
    __shared__ int   s_h[128];
    int b   = blockIdx.y;
    int it0 = blockIdx.x * IPB;
    int nIt = min(IPB, NP - it0);
    int t = threadIdx.x, lane = t & 31, wid = t >> 5;

    if (t < 128) s_h[t] = 0;

    // coalesced float4 staging (alignment-shifted)
    size_t base  = ((size_t)b * NP + it0) * 85;
    size_t first = base & ~(size_t)3;
    int shift = (int)(base - first);
    int nvec  = (shift + nIt * 85 + 3) >> 2;   // never OOB: total floats % 4 == 0
    const float4* src = (const float4*)(pred + first);
    float4* dst = (float4*)s_data;
    for (int i = t; i < nvec; i += 256) dst[i] = src[i];
    __syncthreads();

    // 16 items per warp, reduced from smem
    #pragma unroll 4
    for (int k = 0; k < 16; k++) {
        int il = wid * 16 + k;
        if (il >= nIt) break;
        const float* p = s_data + shift + il * 85;
        float v0 = p[lane];
        float v1 = p[lane + 32];
        float v2 = (lane < 21) ? p[lane + 64] : 0.0f;
        float obj = __shfl_sync(FULLM, v0, 4);

        // packed argmax: value bits << 32 | (255 - slot); max => (max val, min slot)
        u64 k0 = (lane >= 5) ? (((u64)__float_as_uint(v0) << 32) | (u64)(255 - lane)) : 0ull;
        u64 k1 = ((u64)__float_as_uint(v1) << 32) | (u64)(255 - (lane + 32));
        u64 k2 = (lane < 21) ? (((u64)__float_as_uint(v2) << 32) | (u64)(255 - (lane + 64))) : 0ull;
        u64 m = max(k0, max(k1, k2));
        #pragma unroll
        for (int off = 16; off; off >>= 1)
            m = max(m, __shfl_xor_sync(FULLM, m, off));

        if (lane == 0) {
            float bv = __uint_as_float((unsigned)(m >> 32));
            int cls = (255 - (int)(m & 0xFFull)) - 5;
            float score = __fmul_rn(obj, bv);
            bool valid = (obj > 0.25f) && (score > 0.25f);
            unsigned kk = 0xFFFFFFFFu;
            if (valid) {
                unsigned inv = 0x3F800000u - __float_as_uint(score);  // < 0x1000000
                kk = (inv << 7) | (unsigned)cls;
                atomicAdd(&s_h[inv >> 17], 1);
            }
            g_key32[(size_t)b * NP + it0 + il] = kk;
        }
    }
    __syncthreads();
    if (t < 128) {
        int v = s_h[t];
        if (v) atomicAdd(&g_hist[b * 132 + t], v);
    }
}

// ---------------- stage 2: cutoff + chunked ordered compact + sort + gather + class-group ----------------
__global__ void __launch_bounds__(SC_THREADS)
k_sortcompact(const float* __restrict__ pred) {
    typedef cub::BlockRadixSort<unsigned, SC_THREADS, SC_ITEMS, unsigned> BRS;
    __shared__ union {
        struct { unsigned ck[CANDN]; unsigned cv[CANDN]; } c;
        typename BRS::TempStorage sort;
    } u;
    __shared__ int s_hist[128];
    __shared__ int s_cut_sh, s_M;
    __shared__ int s_wsum[32];
    __shared__ int s_ccnt[81], s_cofs[81];

    int b = blockIdx.x, t = threadIdx.x;
    int lane = t & 31, wid = t >> 5;

    if (t < 128) { s_hist[t] = g_hist[b * 132 + t]; g_hist[b * 132 + t] = 0; }
    __syncthreads();
    if (t == 0) {
        int cum = 0, c = 128;
        for (int i = 0; i < 128; i++) {
            cum += s_hist[i];
            if (cum >= TOPKN) { c = i; break; }
        }
        s_cut_sh = c;
    }
    __syncthreads();
    unsigned cut = (unsigned)s_cut_sh;

    // chunked idx-ordered compaction: thread t owns items [25t, 25t+25)
    const int CHUNK = (NP + SC_THREADS - 1) / SC_THREADS;   // 25
    int start = t * CHUNK;
    int lim = min(start + CHUNK, NP);
    int cnt = 0;
    for (int i = start; i < lim; i++)
        if ((g_key32[(size_t)b * NP + i] >> 24) <= cut) cnt++;
    int incl = cnt;
    #pragma unroll
    for (int d = 1; d < 32; d <<= 1) {
        int n = __shfl_up_sync(FULLM, incl, d);
        if (lane >= d) incl += n;
    }
    if (lane == 31) s_wsum[wid] = incl;
    __syncthreads();
    if (t < 32) {
        int v = s_wsum[t], inc2 = v;
        #pragma unroll
        for (int d = 1; d < 32; d <<= 1) {
            int n = __shfl_up_sync(FULLM, inc2, d);
            if (t >= d) inc2 += n;
        }
        s_wsum[t] = inc2 - v;
        if (t == 31) s_M = inc2;
    }
    __syncthreads();
    int off = s_wsum[wid] + incl - cnt;
    for (int i = start; i < lim; i++) {
        unsigned kk = g_key32[(size_t)b * NP + i];
        if ((kk >> 24) <= cut) {
            if (off < CANDN) {
                u.c.ck[off] = kk >> 7;                       // 25-bit inv
                u.c.cv[off] = (unsigned)i | ((kk & 0x7Fu) << 16);
            }
            off++;
        }
    }
    __syncthreads();
    int M = min(s_M, CANDN);

    unsigned keys[SC_ITEMS], vals[SC_ITEMS];
    #pragma unroll
    for (int i = 0; i < SC_ITEMS; i++) {
        int r = t * SC_ITEMS + i;
        keys[i] = (r < M) ? u.c.ck[r] : 0x1FFFFFFu;   // padding sorts last
        vals[i] = (r < M) ? u.c.cv[r] : 0u;
    }
    __syncthreads();
    // stable ascending sort on 25-bit inv; idx-order compaction supplies the tie-break
    BRS(u.sort).Sort(keys, vals, 0, 25);

    if (t < 81) s_ccnt[t] = 0;
    __syncthreads();

    #pragma unroll
    for (int i = 0; i < SC_ITEMS; i++) {
        int r = t * SC_ITEMS + i;
        if (r >= TOPKN) continue;
        int g = b * TOPKN + r;
        unsigned inv = keys[i];
        if (inv >= 0x1000000u) {          // padding: no real candidate at this rank
            g_boxes[g]  = make_float4(0.f, 0.f, 0.f, 0.f);
            g_scores[g] = 0.f;
            g_clsf[g]   = 0.f;
            continue;
        }
        int idx = (int)(vals[i] & 0xFFFFu);
        int cls = (int)(vals[i] >> 16);
        float s = __uint_as_float(0x3F800000u - inv);

        const float* p = pred + ((size_t)b * NP + idx) * 85;
        float cx = p[0], cy = p[1], w = p[2], h = p[3];
        float x1 = __fsub_rn(cx, __fmul_rn(w, 0.5f));
        float y1 = __fsub_rn(cy, __fmul_rn(h, 0.5f));
        float x2 = __fadd_rn(cx, __fmul_rn(w, 0.5f));
        float y2 = __fadd_rn(cy, __fmul_rn(h, 0.5f));

        g_boxes[g]  = make_float4(x1, y1, x2, y2);
        g_scores[g] = s;
        g_clsf[g]   = (float)cls;
        atomicAdd(&s_ccnt[cls], 1);
    }
    __syncthreads();
    if (t == 0) {
        int run = 0;
        for (int c = 0; c < 80; c++) { s_cofs[c] = run; run += s_ccnt[c]; }
        s_cofs[80] = run;
    }
    __syncthreads();
    if (t < 81) g_clsbase[b * 81 + t] = s_cofs[t];
    if (t < 80) s_ccnt[t] = s_cofs[t];   // reuse as running positions
    __syncthreads();
    #pragma unroll
    for (int i = 0; i < SC_ITEMS; i++) {
        int r = t * SC_ITEMS + i;
        if (r >= TOPKN || keys[i] >= 0x1000000u) continue;
        int cls = (int)(vals[i] >> 16);
        int slot = atomicAdd(&s_ccnt[cls], 1);
        g_clsmem[b * TOPKN + slot] = (unsigned)r | ((unsigned)cls << 16);
    }
}

// ---------------- stage 3: within-class IoU edges + Jacobi greedy + output (fused) ----------------
__global__ void __launch_bounds__(256) k_nms(float* __restrict__ out) {
    extern __shared__ char dyn[];
    float4*         s_box   = (float4*)dyn;                          // 2048*16 = 32768
    unsigned*       s_edges = (unsigned*)(dyn + 32768);              // 6144*4  = 24576
    unsigned short* s_rank  = (unsigned short*)(dyn + 32768 + 24576);// 2048*2  = 4096
    int*            s_cb    = (int*)(dyn + 32768 + 24576 + 4096);    // 81*4
    __shared__ int s_ecnt, s_changed;
    __shared__ u64 s_keep[32], s_sup[32];
    __shared__ unsigned s_wbase[32];
    __shared__ unsigned s_total;

    int b = blockIdx.x, t = threadIdx.x;
    int lane = t & 31, wid = t >> 5;

    if (t < 81) s_cb[t] = g_clsbase[b * 81 + t];
    if (t == 0) s_ecnt = 0;
    __syncthreads();
    int total = s_cb[80];

    // load class-grouped, class-shifted boxes
    for (int m = t; m < total; m += 256) {
        unsigned e = g_clsmem[b * TOPKN + m];
        int r = (int)(e & 0xFFFFu), cls = (int)(e >> 16);
        float4 bx = g_boxes[b * TOPKN + r];
        float c = __fmul_rn((float)cls, 4096.0f);
        s_box[m] = make_float4(__fadd_rn(bx.x, c), __fadd_rn(bx.y, c),
                               __fadd_rn(bx.z, c), __fadd_rn(bx.w, c));
        s_rank[m] = (unsigned short)r;
    }
    __syncthreads();

    // within-class pairs, flattened across lanes (one warp per class, round-robin)
    for (int c = wid; c < 80; c += 8) {
        int lo = s_cb[c], n = s_cb[c + 1] - lo;
        int npairs = (n * (n - 1)) >> 1;
        for (int p = lane; p < npairs; p += 32) {
            // triangular decode: find j with j(j-1)/2 <= p < j(j+1)/2
            int j = (int)(0.5f * (1.0f + sqrtf(8.0f * (float)p + 1.0f)));
            while ((j * (j - 1)) >> 1 > p) j--;
            while ((j * (j + 1)) >> 1 <= p) j++;
            int i = p - ((j * (j - 1)) >> 1);

            float4 A = s_box[lo + j];
            float4 B = s_box[lo + i];
            float ltx = fmaxf(A.x, B.x);
            float lty = fmaxf(A.y, B.y);
            float rbx = fminf(A.z, B.z);
            float rby = fminf(A.w, B.w);
            float ww = fmaxf(__fsub_rn(rbx, ltx), 0.0f);
            float hh = fmaxf(__fsub_rn(rby, lty), 0.0f);
            float inter = __fmul_rn(ww, hh);
            if (inter > 0.0f) {
                float areaA = __fmul_rn(__fsub_rn(A.z, A.x), __fsub_rn(A.w, A.y));
                float areaB = __fmul_rn(__fsub_rn(B.z, B.x), __fsub_rn(B.w, B.y));
                float denom = __fadd_rn(__fsub_rn(__fadd_rn(areaA, areaB), inter), 1e-7f);
                bool bit;
                if (inter > __fmul_rn(0.4501f, denom))       bit = true;
                else if (inter <= __fmul_rn(0.4499f, denom)) bit = false;
                else bit = (__fdiv_rn(inter, denom) > 0.45f);
                if (bit) {
                    int ri = s_rank[lo + i], rj = s_rank[lo + j];
                    int lw = min(ri, rj), hi = max(ri, rj);
                    int pos = atomicAdd(&s_ecnt, 1);
                    if (pos < ECAP)
                        s_edges[pos] = ((unsigned)lw << 16) | (unsigned)hi;
                }
            }
        }
    }
    __syncthreads();
    int E = min(s_ecnt, ECAP);

    // all real candidates are valid (invalids excluded upstream)
    if (t < 32) {
        int base = t * 64;
        s_keep[t] = (total >= base + 64) ? ~0ull
                  : (total <= base) ? 0ull : ((1ull << (total - base)) - 1ull);
    }
    __syncthreads();

    // Jacobi fixpoint of keep[j] = valid[j] & !exists edge(i,j) with keep[i] (DAG, i<j)
    int changed;
    do {
        if (t < 32) s_sup[t] = 0ull;
        __syncthreads();
        for (int e = t; e < E; e += 256) {
            unsigned ed = s_edges[e];
            int i = (int)(ed >> 16), j = (int)(ed & 0xFFFFu);
            if ((s_keep[i >> 6] >> (i & 63)) & 1ull)
                atomicOr(&s_sup[j >> 6], 1ull << (j & 63));
        }
        __syncthreads();
        if (t == 0) s_changed = 0;
        __syncthreads();
        if (t < 32) {
            int base = t * 64;
            u64 valid = (total >= base + 64) ? ~0ull
                      : (total <= base) ? 0ull : ((1ull << (total - base)) - 1ull);
            u64 nk = valid & ~s_sup[t];
            if (nk != s_keep[t]) { s_keep[t] = nk; s_changed = 1; }
        }
        __syncthreads();
        changed = s_changed;
    } while (changed);

    // per-word base ranks
    if (wid == 0) {
        unsigned cnt = (unsigned)__popcll(s_keep[lane]), incl = cnt;
        #pragma unroll
        for (int d = 1; d < 32; d <<= 1) {
            unsigned n = __shfl_up_sync(FULLM, incl, d);
            if (lane >= d) incl += n;
        }
        s_wbase[lane] = incl - cnt;
        if (lane == 31) s_total = incl;
    }
    __syncthreads();

    // parallel compaction of survivors (rank order == score order)
    #pragma unroll
    for (int r = 0; r < 8; r++) {
        int gbit = t + 256 * r;
        int word = gbit >> 6, bit = gbit & 63;
        u64 kw = s_keep[word];
        if ((kw >> bit) & 1ull) {
            unsigned rank = s_wbase[word] +
                            (unsigned)__popcll(kw & (((u64)1 << bit) - 1ull));
            if (rank < MAXDET) {
                int g = b * TOPKN + gbit;
                float4 bx = g_boxes[g];
                float* o = out + ((size_t)b * MAXDET + rank) * 6;
                o[0] = bx.x; o[1] = bx.y; o[2] = bx.z; o[3] = bx.w;
                o[4] = g_scores[g];
                o[5] = g_clsf[g];
            }
        }
    }
    unsigned fillstart = min(s_total, (unsigned)MAXDET);
    for (unsigned m = fillstart + t; m < MAXDET; m += 256) {
        float* o = out + ((size_t)b * MAXDET + m) * 6;
        o[0] = 0.f; o[1] = 0.f; o[2] = 0.f; o[3] = 0.f; o[4] = 0.f; o[5] = -1.f;
    }
}

// ---------------- launch ----------------
extern "C" void kernel_launch(void* const* d_in, const int* in_sizes, int n_in,
                              void* d_out, int out_size) {
    (void)in_sizes; (void)n_in; (void)out_size;
    const float* pred = (const float*)d_in[0];
    float* out = (float*)d_out;

    const int DYN = 32768 + 24576 + 4096 + 81 * 4;
    static bool attr_set = false;
    if (!attr_set) {
        cudaFuncSetAttribute(k_nms, cudaFuncAttributeMaxDynamicSharedMemorySize, DYN);
        attr_set = true;
    }

    k_score<<<dim3((NP + IPB - 1) / IPB, BATCH), 256>>>(pred);
    k_sortcompact<<<BATCH, SC_THREADS>>>(pred);
    k_nms<<<BATCH, 256, DYN>>>(out);
}

// round 8
// speedup vs baseline: 1.4920x; 1.1576x over previous
#include <cuda_runtime.h>
#include <cub/cub.cuh>
#include <cstdint>

#define BATCH  16
#define NP     25200
#define TOPKN  2048
#define MAXDET 1000
#define CANDN  3072
#define ECAP   6144
#define IPB    128
#define SC_THREADS 1024
#define SC_ITEMS   3
#define FULLM  0xffffffffu
typedef unsigned long long u64;

// ---------------- scratch (static device globals) ----------------
__device__ unsigned g_key32[BATCH * NP];       // (inv<<7)|cls, 0xFFFFFFFF = invalid
__device__ int      g_hist[BATCH * 132];       // bucket = inv>>17 (valid only); reset in k_sortcompact
__device__ float4   g_boxes[BATCH * TOPKN];    // unshifted xyxy, rank-ordered
__device__ float    g_scores[BATCH * TOPKN];
__device__ float    g_clsf[BATCH * TOPKN];
__device__ unsigned g_clsmem[BATCH * TOPKN];   // class-grouped: rank | (cls<<16)
__device__ int      g_clsbase[BATCH * 81];     // per-class segment offsets (+ total at [80])

// ---------------- stage 1: thread-per-item score/class/key ----------------
__global__ void __launch_bounds__(IPB) k_score(const float* __restrict__ pred) {
    __shared__ float s_data[IPB * 85 + 4];
    __shared__ int   s_h[128];
    int b   = blockIdx.y;
    int it0 = blockIdx.x * IPB;
    int nIt = min(IPB, NP - it0);
    int t = threadIdx.x;

    if (t < 128) s_h[t] = 0;

    // coalesced float4 staging (alignment-shifted)
    size_t base  = ((size_t)b * NP + it0) * 85;
    size_t first = base & ~(size_t)3;
    int shift = (int)(base - first);
    int nvec  = (shift + nIt * 85 + 3) >> 2;   // never OOB: total float count % 4 == 0
    const float4* src = (const float4*)(pred + first);
    float4* dst = (float4*)s_data;
    for (int i = t; i < nvec; i += IPB) dst[i] = src[i];
    __syncthreads();

    if (t < nIt) {
        const float* p = s_data + shift + t * 85;   // stride 85: bank-conflict-free
        float obj = p[4];

        // pass 1: max over 80 class slots, 4 independent chains
        float m0 = p[5],  m1 = p[6],  m2 = p[7],  m3 = p[8];
        #pragma unroll
        for (int k = 9; k < 85; k += 4) {
            m0 = fmaxf(m0, p[k]);
            m1 = fmaxf(m1, p[k + 1]);
            m2 = fmaxf(m2, p[k + 2]);
            m3 = fmaxf(m3, p[k + 3]);
        }
        float bv = fmaxf(fmaxf(m0, m1), fmaxf(m2, m3));

        // pass 2: lowest index attaining bv (backward predicated scan)
        int bi = 0;
        #pragma unroll
        for (int k = 79; k >= 0; k--)
            if (p[5 + k] == bv) bi = k;

        float score = __fmul_rn(obj, bv);
        bool valid = (obj > 0.25f) && (score > 0.25f);
        unsigned kk = 0xFFFFFFFFu;
        if (valid) {
            unsigned inv = 0x3F800000u - __float_as_uint(score);  // < 0x1000000
            kk = (inv << 7) | (unsigned)bi;
            atomicAdd(&s_h[inv >> 17], 1);
        }
        g_key32[(size_t)b * NP + it0 + t] = kk;
    }
    __syncthreads();
    if (t < 128) {
        int v = s_h[t];
        if (v) atomicAdd(&g_hist[b * 132 + t], v);
    }
}

// ---------------- stage 2: cutoff + chunked ordered compact + sort + gather + class-group ----------------
__global__ void __launch_bounds__(SC_THREADS)
k_sortcompact(const float* __restrict__ pred) {
    typedef cub::BlockRadixSort<unsigned, SC_THREADS, SC_ITEMS, unsigned> BRS;
    __shared__ union {
        struct { unsigned ck[CANDN]; unsigned cv[CANDN]; } c;
        typename BRS::TempStorage sort;
    } u;
    __shared__ int s_hist[128];
    __shared__ int s_cut_sh, s_M;
    __shared__ int s_wsum[32];
    __shared__ int s_ccnt[81], s_cofs[81];

    int b = blockIdx.x, t = threadIdx.x;
    int lane = t & 31, wid = t >> 5;

    if (t < 128) { s_hist[t] = g_hist[b * 132 + t]; g_hist[b * 132 + t] = 0; }
    __syncthreads();
    if (t == 0) {
        int cum = 0, c = 128;
        for (int i = 0; i < 128; i++) {
            cum += s_hist[i];
            if (cum >= TOPKN) { c = i; break; }
        }
        s_cut_sh = c;
    }
    __syncthreads();
    unsigned cut = (unsigned)s_cut_sh;
    // dynamic sort width: all kept inv < (cut+1)<<17
    int end_bit = 32 - __clz((int)(((cut + 1u) << 17) - 1u));
    if (end_bit > 25) end_bit = 25;

    // chunked idx-ordered compaction: thread t owns items [25t, 25t+25)
    const int CHUNK = (NP + SC_THREADS - 1) / SC_THREADS;   // 25
    int start = t * CHUNK;
    int lim = min(start + CHUNK, NP);
    int cnt = 0;
    for (int i = start; i < lim; i++)
        if ((g_key32[(size_t)b * NP + i] >> 24) <= cut) cnt++;
    int incl = cnt;
    #pragma unroll
    for (int d = 1; d < 32; d <<= 1) {
        int n = __shfl_up_sync(FULLM, incl, d);
        if (lane >= d) incl += n;
    }
    if (lane == 31) s_wsum[wid] = incl;
    __syncthreads();
    if (t < 32) {
        int v = s_wsum[t], inc2 = v;
        #pragma unroll
        for (int d = 1; d < 32; d <<= 1) {
            int n = __shfl_up_sync(FULLM, inc2, d);
            if (t >= d) inc2 += n;
        }
        s_wsum[t] = inc2 - v;
        if (t == 31) s_M = inc2;
    }
    __syncthreads();
    int off = s_wsum[wid] + incl - cnt;
    for (int i = start; i < lim; i++) {
        unsigned kk = g_key32[(size_t)b * NP + i];
        if ((kk >> 24) <= cut) {
            if (off < CANDN) {
                u.c.ck[off] = kk >> 7;                       // 25-bit inv
                u.c.cv[off] = (unsigned)i | ((kk & 0x7Fu) << 16);
            }
            off++;
        }
    }
    __syncthreads();
    int M = min(s_M, CANDN);

    unsigned keys[SC_ITEMS], vals[SC_ITEMS];
    #pragma unroll
    for (int i = 0; i < SC_ITEMS; i++) {
        int r = t * SC_ITEMS + i;
        keys[i] = (r < M) ? u.c.ck[r] : 0x1FFFFFFu;   // padding sorts last
        vals[i] = (r < M) ? u.c.cv[r] : 0u;
    }
    __syncthreads();
    // stable ascending sort on inv; idx-order compaction supplies the tie-break.
    // padding keys exceed ((cut+1)<<17)-1 only in bits >= end_bit?  No: pad = 0x1FFFFFF
    // has all low bits set, so sort on full 25 bits when padding present.
    int pad = (M < CANDN) ? 25 : end_bit;
    BRS(u.sort).Sort(keys, vals, 0, pad);

    if (t < 81) s_ccnt[t] = 0;
    __syncthreads();

    #pragma unroll
    for (int i = 0; i < SC_ITEMS; i++) {
        int r = t * SC_ITEMS + i;
        if (r >= TOPKN) continue;
        int g = b * TOPKN + r;
        unsigned inv = keys[i];
        if (inv >= 0x1000000u) {          // padding: no real candidate at this rank
            g_boxes[g]  = make_float4(0.f, 0.f, 0.f, 0.f);
            g_scores[g] = 0.f;
            g_clsf[g]   = 0.f;
            continue;
        }
        int idx = (int)(vals[i] & 0xFFFFu);
        int cls = (int)(vals[i] >> 16);
        float s = __uint_as_float(0x3F800000u - inv);

        const float* p = pred + ((size_t)b * NP + idx) * 85;
        float cx = p[0], cy = p[1], w = p[2], h = p[3];
        float x1 = __fsub_rn(cx, __fmul_rn(w, 0.5f));
        float y1 = __fsub_rn(cy, __fmul_rn(h, 0.5f));
        float x2 = __fadd_rn(cx, __fmul_rn(w, 0.5f));
        float y2 = __fadd_rn(cy, __fmul_rn(h, 0.5f));

        g_boxes[g]  = make_float4(x1, y1, x2, y2);
        g_scores[g] = s;
        g_clsf[g]   = (float)cls;
        atomicAdd(&s_ccnt[cls], 1);
    }
    __syncthreads();
    if (t == 0) {
        int run = 0;
        for (int c = 0; c < 80; c++) { s_cofs[c] = run; run += s_ccnt[c]; }
        s_cofs[80] = run;
    }
    __syncthreads();
    if (t < 81) g_clsbase[b * 81 + t] = s_cofs[t];
    if (t < 80) s_ccnt[t] = s_cofs[t];   // reuse as running positions
    __syncthreads();
    #pragma unroll
    for (int i = 0; i < SC_ITEMS; i++) {
        int r = t * SC_ITEMS + i;
        if (r >= TOPKN || keys[i] >= 0x1000000u) continue;
        int cls = (int)(vals[i] >> 16);
        int slot = atomicAdd(&s_ccnt[cls], 1);
        g_clsmem[b * TOPKN + slot] = (unsigned)r | ((unsigned)cls << 16);
    }
}

// ---------------- stage 3: within-class IoU edges + Jacobi greedy + output (fused) ----------------
__global__ void __launch_bounds__(256) k_nms(float* __restrict__ out) {
    extern __shared__ char dyn[];
    float4*         s_box   = (float4*)dyn;                          // 2048*16 = 32768
    unsigned*       s_edges = (unsigned*)(dyn + 32768);              // 6144*4  = 24576
    unsigned short* s_rank  = (unsigned short*)(dyn + 32768 + 24576);// 2048*2  = 4096
    int*            s_cb    = (int*)(dyn + 32768 + 24576 + 4096);    // 81*4
    __shared__ int s_ecnt, s_changed;
    __shared__ u64 s_keep[32], s_sup[32];
    __shared__ unsigned s_wbase[32];
    __shared__ unsigned s_total;

    int b = blockIdx.x, t = threadIdx.x;
    int lane = t & 31, wid = t >> 5;

    if (t < 81) s_cb[t] = g_clsbase[b * 81 + t];
    if (t == 0) s_ecnt = 0;
    __syncthreads();
    int total = s_cb[80];

    // load class-grouped, class-shifted boxes
    for (int m = t; m < total; m += 256) {
        unsigned e = g_clsmem[b * TOPKN + m];
        int r = (int)(e & 0xFFFFu), cls = (int)(e >> 16);
        float4 bx = g_boxes[b * TOPKN + r];
        float c = __fmul_rn((float)cls, 4096.0f);
        s_box[m] = make_float4(__fadd_rn(bx.x, c), __fadd_rn(bx.y, c),
                               __fadd_rn(bx.z, c), __fadd_rn(bx.w, c));
        s_rank[m] = (unsigned short)r;
    }
    __syncthreads();

    // within-class pairs, flattened across lanes (one warp per class, round-robin)
    for (int c = wid; c < 80; c += 8) {
        int lo = s_cb[c], n = s_cb[c + 1] - lo;
        int npairs = (n * (n - 1)) >> 1;
        for (int p = lane; p < npairs; p += 32) {
            // triangular decode: find j with j(j-1)/2 <= p < j(j+1)/2
            int j = (int)(0.5f * (1.0f + sqrtf(8.0f * (float)p + 1.0f)));
            while ((j * (j - 1)) >> 1 > p) j--;
            while ((j * (j + 1)) >> 1 <= p) j++;
            int i = p - ((j * (j - 1)) >> 1);

            float4 A = s_box[lo + j];
            float4 B = s_box[lo + i];
            float ltx = fmaxf(A.x, B.x);
            float lty = fmaxf(A.y, B.y);
            float rbx = fminf(A.z, B.z);
            float rby = fminf(A.w, B.w);
            float ww = fmaxf(__fsub_rn(rbx, ltx), 0.0f);
            float hh = fmaxf(__fsub_rn(rby, lty), 0.0f);
            float inter = __fmul_rn(ww, hh);
            if (inter > 0.0f) {
                float areaA = __fmul_rn(__fsub_rn(A.z, A.x), __fsub_rn(A.w, A.y));
                float areaB = __fmul_rn(__fsub_rn(B.z, B.x), __fsub_rn(B.w, B.y));
                float denom = __fadd_rn(__fsub_rn(__fadd_rn(areaA, areaB), inter), 1e-7f);
                bool bit;
                if (inter > __fmul_rn(0.4501f, denom))       bit = true;
                else if (inter <= __fmul_rn(0.4499f, denom)) bit = false;
                else bit = (__fdiv_rn(inter, denom) > 0.45f);
                if (bit) {
                    int ri = s_rank[lo + i], rj = s_rank[lo + j];
                    int lw = min(ri, rj), hi = max(ri, rj);
                    int pos = atomicAdd(&s_ecnt, 1);
                    if (pos < ECAP)
                        s_edges[pos] = ((unsigned)lw << 16) | (unsigned)hi;
                }
            }
        }
    }
    __syncthreads();
    int E = min(s_ecnt, ECAP);

    // all real candidates are valid (invalids excluded upstream)
    if (t < 32) {
        int base = t * 64;
        s_keep[t] = (total >= base + 64) ? ~0ull
                  : (total <= base) ? 0ull : ((1ull << (total - base)) - 1ull);
    }
    __syncthreads();

    // Jacobi fixpoint of keep[j] = valid[j] & !exists edge(i,j) with keep[i] (DAG, i<j)
    int changed;
    do {
        if (t < 32) s_sup[t] = 0ull;
        __syncthreads();
        for (int e = t; e < E; e += 256) {
            unsigned ed = s_edges[e];
            int i = (int)(ed >> 16), j = (int)(ed & 0xFFFFu);
            if ((s_keep[i >> 6] >> (i & 63)) & 1ull)
                atomicOr(&s_sup[j >> 6], 1ull << (j & 63));
        }
        __syncthreads();
        if (t == 0) s_changed = 0;
        __syncthreads();
        if (t < 32) {
            int base = t * 64;
            u64 valid = (total >= base + 64) ? ~0ull
                      : (total <= base) ? 0ull : ((1ull << (total - base)) - 1ull);
            u64 nk = valid & ~s_sup[t];
            if (nk != s_keep[t]) { s_keep[t] = nk; s_changed = 1; }
        }
        __syncthreads();
        changed = s_changed;
    } while (changed);

    // per-word base ranks
    if (wid == 0) {
        unsigned cnt = (unsigned)__popcll(s_keep[lane]), incl = cnt;
        #pragma unroll
        for (int d = 1; d < 32; d <<= 1) {
            unsigned n = __shfl_up_sync(FULLM, incl, d);
            if (lane >= d) incl += n;
        }
        s_wbase[lane] = incl - cnt;
        if (lane == 31) s_total = incl;
    }
    __syncthreads();

    // parallel compaction of survivors (rank order == score order)
    #pragma unroll
    for (int r = 0; r < 8; r++) {
        int gbit = t + 256 * r;
        int word = gbit >> 6, bit = gbit & 63;
        u64 kw = s_keep[word];
        if ((kw >> bit) & 1ull) {
            unsigned rank = s_wbase[word] +
                            (unsigned)__popcll(kw & (((u64)1 << bit) - 1ull));
            if (rank < MAXDET) {
                int g = b * TOPKN + gbit;
                float4 bx = g_boxes[g];
                float* o = out + ((size_t)b * MAXDET + rank) * 6;
                o[0] = bx.x; o[1] = bx.y; o[2] = bx.z; o[3] = bx.w;
                o[4] = g_scores[g];
                o[5] = g_clsf[g];
            }
        }
    }
    unsigned fillstart = min(s_total, (unsigned)MAXDET);
    for (unsigned m = fillstart + t; m < MAXDET; m += 256) {
        float* o = out + ((size_t)b * MAXDET + m) * 6;
        o[0] = 0.f; o[1] = 0.f; o[2] = 0.f; o[3] = 0.f; o[4] = 0.f; o[5] = -1.f;
    }
}

// ---------------- launch ----------------
extern "C" void kernel_launch(void* const* d_in, const int* in_sizes, int n_in,
                              void* d_out, int out_size) {
    (void)in_sizes; (void)n_in; (void)out_size;
    const float* pred = (const float*)d_in[0];
    float* out = (float*)d_out;

    const int DYN = 32768 + 24576 + 4096 + 81 * 4;
    static bool attr_set = false;
    if (!attr_set) {
        cudaFuncSetAttribute(k_nms, cudaFuncAttributeMaxDynamicSharedMemorySize, DYN);
        attr_set = true;
    }

    k_score<<<dim3((NP + IPB - 1) / IPB, BATCH), IPB>>>(pred);
    k_sortcompact<<<BATCH, SC_THREADS>>>(pred);
    k_nms<<<BATCH, 256, DYN>>>(out);
}

// round 9
// speedup vs baseline: 2.0781x; 1.3928x over previous
#include <cuda_runtime.h>
#include <cub/cub.cuh>
#include <cstdint>

#define BATCH  16
#define NP     25200
#define TOPKN  2048
#define MAXDET 1000
#define CANDN  3072
#define ECAP   6144
#define IPB    128
#define STH    256
#define SN     1024
#define FULLM  0xffffffffu
typedef unsigned long long u64;

// ---------------- scratch ----------------
__device__ unsigned g_key32[BATCH * NP];   // (inv<<7)|cls, 0xFFFFFFFF = invalid
__device__ int      g_hist[BATCH * 132];   // bucket = inv>>17 (valid only); reset in k_sortnms

// ---------------- stage 1: thread-per-item score/class/key (256 thr, 128 items) ----------------
__global__ void __launch_bounds__(STH, 4) k_score(const float* __restrict__ pred) {
    __shared__ float s_data[IPB * 85 + 4];
    __shared__ int   s_h[128];
    int b   = blockIdx.y;
    int it0 = blockIdx.x * IPB;
    int nIt = min(IPB, NP - it0);
    int t = threadIdx.x;

    if (t < 128) s_h[t] = 0;

    // coalesced float4 staging (alignment-shifted)
    size_t base  = ((size_t)b * NP + it0) * 85;
    size_t first = base & ~(size_t)3;
    int shift = (int)(base - first);
    int nvec  = (shift + nIt * 85 + 3) >> 2;   // never OOB: total float count % 4 == 0
    const float4* src = (const float4*)(pred + first);
    float4* dst = (float4*)s_data;
    for (int i = t; i < nvec; i += STH) dst[i] = src[i];
    __syncthreads();

    if (t < nIt) {
        const float* p = s_data + shift + t * 85;   // stride 85: bank-conflict-free
        float obj = p[4];

        // pass 1: max over 80 class slots, 4 independent chains
        float m0 = p[5],  m1 = p[6],  m2 = p[7],  m3 = p[8];
        #pragma unroll
        for (int k = 9; k < 85; k += 4) {
            m0 = fmaxf(m0, p[k]);
            m1 = fmaxf(m1, p[k + 1]);
            m2 = fmaxf(m2, p[k + 2]);
            m3 = fmaxf(m3, p[k + 3]);
        }
        float bv = fmaxf(fmaxf(m0, m1), fmaxf(m2, m3));

        // pass 2: lowest index attaining bv (backward predicated scan)
        int bi = 0;
        #pragma unroll 8
        for (int k = 79; k >= 0; k--)
            if (p[5 + k] == bv) bi = k;

        float score = __fmul_rn(obj, bv);
        bool valid = (obj > 0.25f) && (score > 0.25f);
        unsigned kk = 0xFFFFFFFFu;
        if (valid) {
            unsigned inv = 0x3F800000u - __float_as_uint(score);  // < 0x1000000
            kk = (inv << 7) | (unsigned)bi;
            atomicAdd(&s_h[inv >> 17], 1);
        }
        g_key32[(size_t)b * NP + it0 + t] = kk;
    }
    __syncthreads();
    if (t < 128) {
        int v = s_h[t];
        if (v) atomicAdd(&g_hist[b * 132 + t], v);
    }
}

// ---------------- stage 2: cutoff+compact+sort+gather+class-group+IoU+greedy+output ----------------
typedef cub::BlockRadixSort<unsigned, SN, 3, unsigned> BRS;
struct SMem {
    union {
        struct { unsigned ck[CANDN]; unsigned cv[CANDN]; } c;   // pre-sort staging
        BRS::TempStorage sort;                                  // sort temp
        float4 sbox[TOPKN];                                     // shifted, class-grouped (post-sort)
    } a;
    float4        obox[TOPKN];      // unshifted, rank-ordered
    float         score[TOPKN];
    unsigned short rnk[TOPKN];      // class-grouped -> rank
    unsigned char cls8[TOPKN];
    unsigned      edges[ECAP];
};

__global__ void __launch_bounds__(SN) k_sortnms(const float* __restrict__ pred,
                                                float* __restrict__ out) {
    extern __shared__ char raw[];
    SMem* sm = (SMem*)raw;
    __shared__ int s_hist[128], s_wsum[32];
    __shared__ int s_cut, s_M;
    __shared__ int s_ccnt[81], s_cofs[81];
    __shared__ int s_ecnt, s_changed;
    __shared__ u64 s_keep[32], s_sup[32];
    __shared__ unsigned s_wbase[32], s_total;

    int b = blockIdx.x, t = threadIdx.x;
    int lane = t & 31, wid = t >> 5;

    if (t < 128) { s_hist[t] = g_hist[b * 132 + t]; g_hist[b * 132 + t] = 0; }
    __syncthreads();
    if (t == 0) {
        int cum = 0, c = 128;
        for (int i = 0; i < 128; i++) {
            cum += s_hist[i];
            if (cum >= TOPKN) { c = i; break; }
        }
        s_cut = c;
        s_ecnt = 0;
    }
    __syncthreads();
    unsigned cut = (unsigned)s_cut;
    unsigned limit = min((cut + 1u) << 17, 1u << 24);
    int end_bit = 32 - __clz(limit - 1u);

    // chunked idx-ordered compaction: thread t owns items [25t, 25t+25)
    const int CHUNK = (NP + SN - 1) / SN;   // 25
    int start = t * CHUNK;
    int lim = min(start + CHUNK, NP);
    int cnt = 0;
    for (int i = start; i < lim; i++)
        if ((g_key32[(size_t)b * NP + i] >> 24) <= cut) cnt++;
    int incl = cnt;
    #pragma unroll
    for (int d = 1; d < 32; d <<= 1) {
        int n = __shfl_up_sync(FULLM, incl, d);
        if (lane >= d) incl += n;
    }
    if (lane == 31) s_wsum[wid] = incl;
    __syncthreads();
    if (t < 32) {
        int v = s_wsum[t], inc2 = v;
        #pragma unroll
        for (int d = 1; d < 32; d <<= 1) {
            int n = __shfl_up_sync(FULLM, inc2, d);
            if (t >= d) inc2 += n;
        }
        s_wsum[t] = inc2 - v;
        if (t == 31) s_M = inc2;
    }
    __syncthreads();
    int off = s_wsum[wid] + incl - cnt;
    for (int i = start; i < lim; i++) {
        unsigned kk = g_key32[(size_t)b * NP + i];
        if ((kk >> 24) <= cut) {
            if (off < CANDN) {
                sm->a.c.ck[off] = kk >> 7;                       // 25-bit inv
                sm->a.c.cv[off] = (unsigned)i | ((kk & 0x7Fu) << 16);
            }
            off++;
        }
    }
    __syncthreads();
    int M = min(s_M, CANDN);

    unsigned keys[3], vals[3];
    #pragma unroll
    for (int i = 0; i < 3; i++) {
        int r = t * 3 + i;
        keys[i] = (r < M) ? sm->a.c.ck[r] : (limit - 1u);  // pad: max key within end_bit
        vals[i] = (r < M) ? sm->a.c.cv[r] : 0xFFFFFFFFu;   // sentinel marks padding
    }
    __syncthreads();
    // stable ascending sort on inv (end_bit bits); idx-order compaction = tie-break;
    // pads tie at max key but follow all real items (stability).
    BRS(sm->a.sort).Sort(keys, vals, 0, end_bit);

    if (t < 81) s_ccnt[t] = 0;
    __syncthreads();

    // gather top-2048 into smem (rank-ordered)
    #pragma unroll
    for (int i = 0; i < 3; i++) {
        int r = t * 3 + i;
        if (r >= TOPKN) continue;
        if (vals[i] >> 31) {                // padding
            sm->obox[r]  = make_float4(0.f, 0.f, 0.f, 0.f);
            sm->score[r] = 0.f;
            sm->cls8[r]  = 0;
            continue;
        }
        int idx = (int)(vals[i] & 0xFFFFu);
        int cls = (int)((vals[i] >> 16) & 0x7Fu);
        float s = __uint_as_float(0x3F800000u - keys[i]);

        const float* p = pred + ((size_t)b * NP + idx) * 85;
        float cx = p[0], cy = p[1], w = p[2], h = p[3];
        float x1 = __fsub_rn(cx, __fmul_rn(w, 0.5f));
        float y1 = __fsub_rn(cy, __fmul_rn(h, 0.5f));
        float x2 = __fadd_rn(cx, __fmul_rn(w, 0.5f));
        float y2 = __fadd_rn(cy, __fmul_rn(h, 0.5f));

        sm->obox[r]  = make_float4(x1, y1, x2, y2);
        sm->score[r] = s;
        sm->cls8[r]  = (unsigned char)cls;
        atomicAdd(&s_ccnt[cls], 1);
    }
    __syncthreads();
    if (t == 0) {
        int run = 0;
        for (int c = 0; c < 80; c++) { s_cofs[c] = run; run += s_ccnt[c]; }
        s_cofs[80] = run;
    }
    __syncthreads();
    int total = s_cofs[80];
    if (t < 80) s_ccnt[t] = s_cofs[t];   // running positions
    __syncthreads();

    // class-grouped scatter of shifted boxes (overlays dead sort temp)
    #pragma unroll
    for (int i = 0; i < 3; i++) {
        int r = t * 3 + i;
        if (r >= TOPKN || (vals[i] >> 31)) continue;
        int cls = (int)((vals[i] >> 16) & 0x7Fu);
        int slot = atomicAdd(&s_ccnt[cls], 1);
        float4 bx = sm->obox[r];
        float c = __fmul_rn((float)cls, 4096.0f);
        sm->a.sbox[slot] = make_float4(__fadd_rn(bx.x, c), __fadd_rn(bx.y, c),
                                       __fadd_rn(bx.z, c), __fadd_rn(bx.w, c));
        sm->rnk[slot] = (unsigned short)r;
    }
    __syncthreads();

    // within-class pairs flattened across lanes; 32 warps over 80 classes
    for (int c = wid; c < 80; c += 32) {
        int lo = s_cofs[c], n = s_cofs[c + 1] - lo;
        int npairs = (n * (n - 1)) >> 1;
        for (int p = lane; p < npairs; p += 32) {
            int j = (int)(0.5f * (1.0f + sqrtf(8.0f * (float)p + 1.0f)));
            while ((j * (j - 1)) >> 1 > p) j--;
            while ((j * (j + 1)) >> 1 <= p) j++;
            int i = p - ((j * (j - 1)) >> 1);

            float4 A = sm->a.sbox[lo + j];
            float4 B = sm->a.sbox[lo + i];
            float ltx = fmaxf(A.x, B.x);
            float lty = fmaxf(A.y, B.y);
            float rbx = fminf(A.z, B.z);
            float rby = fminf(A.w, B.w);
            float ww = fmaxf(__fsub_rn(rbx, ltx), 0.0f);
            float hh = fmaxf(__fsub_rn(rby, lty), 0.0f);
            float inter = __fmul_rn(ww, hh);
            if (inter > 0.0f) {
                float areaA = __fmul_rn(__fsub_rn(A.z, A.x), __fsub_rn(A.w, A.y));
                float areaB = __fmul_rn(__fsub_rn(B.z, B.x), __fsub_rn(B.w, B.y));
                float denom = __fadd_rn(__fsub_rn(__fadd_rn(areaA, areaB), inter), 1e-7f);
                bool bit;
                if (inter > __fmul_rn(0.4501f, denom))       bit = true;
                else if (inter <= __fmul_rn(0.4499f, denom)) bit = false;
                else bit = (__fdiv_rn(inter, denom) > 0.45f);
                if (bit) {
                    int ri = sm->rnk[lo + i], rj = sm->rnk[lo + j];
                    int lw = min(ri, rj), hi = max(ri, rj);
                    int pos = atomicAdd(&s_ecnt, 1);
                    if (pos < ECAP)
                        sm->edges[pos] = ((unsigned)lw << 16) | (unsigned)hi;
                }
            }
        }
    }
    __syncthreads();
    int E = min(s_ecnt, ECAP);

    if (t < 32) {
        int base = t * 64;
        s_keep[t] = (total >= base + 64) ? ~0ull
                  : (total <= base) ? 0ull : ((1ull << (total - base)) - 1ull);
    }
    __syncthreads();

    // Jacobi fixpoint of keep[j] = valid[j] & !exists edge(i,j) with keep[i] (DAG, i<j)
    int changed;
    do {
        if (t < 32) s_sup[t] = 0ull;
        __syncthreads();
        for (int e = t; e < E; e += SN) {
            unsigned ed = sm->edges[e];
            int i = (int)(ed >> 16), j = (int)(ed & 0xFFFFu);
            if ((s_keep[i >> 6] >> (i & 63)) & 1ull)
                atomicOr(&s_sup[j >> 6], 1ull << (j & 63));
        }
        __syncthreads();
        if (t == 0) s_changed = 0;
        __syncthreads();
        if (t < 32) {
            int base = t * 64;
            u64 valid = (total >= base + 64) ? ~0ull
                      : (total <= base) ? 0ull : ((1ull << (total - base)) - 1ull);
            u64 nk = valid & ~s_sup[t];
            if (nk != s_keep[t]) { s_keep[t] = nk; s_changed = 1; }
        }
        __syncthreads();
        changed = s_changed;
    } while (changed);

    // per-word base ranks
    if (wid == 0) {
        unsigned cnt2 = (unsigned)__popcll(s_keep[lane]), incl2 = cnt2;
        #pragma unroll
        for (int d = 1; d < 32; d <<= 1) {
            unsigned n = __shfl_up_sync(FULLM, incl2, d);
            if (lane >= d) incl2 += n;
        }
        s_wbase[lane] = incl2 - cnt2;
        if (lane == 31) s_total = incl2;
    }
    __syncthreads();

    // parallel compaction of survivors (rank order == score order)
    #pragma unroll
    for (int r = 0; r < 2; r++) {
        int gbit = t + SN * r;
        int word = gbit >> 6, bit = gbit & 63;
        u64 kw = s_keep[word];
        if ((kw >> bit) & 1ull) {
            unsigned rank = s_wbase[word] +
                            (unsigned)__popcll(kw & (((u64)1 << bit) - 1ull));
            if (rank < MAXDET) {
                float4 bx = sm->obox[gbit];
                float* o = out + ((size_t)b * MAXDET + rank) * 6;
                o[0] = bx.x; o[1] = bx.y; o[2] = bx.z; o[3] = bx.w;
                o[4] = sm->score[gbit];
                o[5] = (float)sm->cls8[gbit];
            }
        }
    }
    unsigned fillstart = min(s_total, (unsigned)MAXDET);
    for (unsigned m = fillstart + t; m < MAXDET; m += SN) {
        float* o = out + ((size_t)b * MAXDET + m) * 6;
        o[0] = 0.f; o[1] = 0.f; o[2] = 0.f; o[3] = 0.f; o[4] = 0.f; o[5] = -1.f;
    }
}

// ---------------- launch ----------------
extern "C" void kernel_launch(void* const* d_in, const int* in_sizes, int n_in,
                              void* d_out, int out_size) {
    (void)in_sizes; (void)n_in; (void)out_size;
    const float* pred = (const float*)d_in[0];
    float* out = (float*)d_out;

    static bool attr_set = false;
    if (!attr_set) {
        cudaFuncSetAttribute(k_sortnms, cudaFuncAttributeMaxDynamicSharedMemorySize,
                             (int)sizeof(SMem));
        attr_set = true;
    }

    k_score<<<dim3((NP + IPB - 1) / IPB, BATCH), STH>>>(pred);
    k_sortnms<<<BATCH, SN, sizeof(SMem)>>>(pred, out);
}